// round 11
// baseline (speedup 1.0000x reference)
#include <cuda_runtime.h>
#include <cstdint>
#include <cstddef>

// Problem constants
#define NODES   49152
#define FDIM    128
#define DTOT    9
#define NB      12      // nodes per CTA
#define THREADS 768     // 6 groups x 128 threads; each group handles 2 nodes (1 packed pair)

typedef unsigned long long ull;

// packed f32x2 helpers (sm_103a)
#define FMA2(d_, a_, b_, c_) \
    asm("fma.rn.f32x2 %0, %1, %2, %3;" : "=l"(d_) : "l"(a_), "l"(b_), "l"(c_))
#define PACKDUP(d_, f_) \
    asm("mov.b64 %0, {%1, %1};" : "=l"(d_) : "r"(__float_as_uint(f_)))
#define UNPACK2(lo_, hi_, x_) \
    asm("mov.b64 {%0, %1}, %2;" : "=r"(lo_), "=r"(hi_) : "l"(x_))

// smem float map (total 52992 floats = 211968 bytes)
//  T_s : [128 u][9 d][12 n] = 13824   (later overlaid by TU [12 n][1152])
//  SBt : [128 v][12 n]      =  1536
//  PB  : [12 n][256]        =  3072
//  SS2 : [128 c][12 n]      =  1536
//  WREG: 33024  (3 weight chunks 128x65 | ls_w 256x129 | lvw 128x129)
#define OFF_T    0
#define OFF_SBT  13824
#define OFF_PB   15360
#define OFF_SS2  18432
#define OFF_WREG 19968
#define SMEM_FLOATS 52992
#define WPITCH   65
#define WTILE    8320      // 128*65

// stage one 128x64 u-chunk of a weight matrix, untransposed [v][65], conflict-free
static __device__ __forceinline__ void stage_wchunk(float* __restrict__ dst,
                                                    const float* __restrict__ src,
                                                    int chunk, int tid) {
    const float* s = src + chunk * 64;
    for (int i = tid; i < 8192; i += THREADS) {       // 128 v x 64 u
        int vrow = i >> 6;
        int ul   = i & 63;
        dst[vrow * WPITCH + ul] = s[vrow * 128 + ul]; // LDG coalesced; STS banks (v+u)%32
    }
}

// fused q/k/v accumulation for one irrep block over one 64-u chunk (1 node pair)
template<int OFF, int DD>
static __device__ __forceinline__ void fused_chunk(const float* __restrict__ T_s,
                                                   const float* __restrict__ WQc,
                                                   const float* __restrict__ WKc,
                                                   const float* __restrict__ WVc,
                                                   int v, int ng, int chunk,
                                                   ull aq[DD], ull ak[DD], ull av[DD]) {
    const int ubase = chunk * 64;
    #pragma unroll 2
    for (int ul = 0; ul < 64; ul++) {
        float wq = WQc[v * WPITCH + ul];
        float wk = WKc[v * WPITCH + ul];
        float wv = WVc[v * WPITCH + ul];
        ull wq2, wk2, wv2;
        PACKDUP(wq2, wq);
        PACKDUP(wk2, wk);
        PACKDUP(wv2, wv);
        const float* tb = T_s + ((ubase + ul) * 9 + OFF) * 12 + ng;
        #pragma unroll
        for (int d = 0; d < DD; d++) {
            ull t = *reinterpret_cast<const ull*>(tb + d * 12);   // LDS.64, 8B-aligned
            FMA2(aq[d], wq2, t, aq[d]);
            FMA2(ak[d], wk2, t, ak[d]);
            FMA2(av[d], wv2, t, av[d]);
        }
    }
}

template<int DD>
static __device__ __forceinline__ void finalize_qk(ull aq[DD], ull ak[DD],
                                                   float cf, float s_reg[2]) {
    ull acc = 0ull;
    #pragma unroll
    for (int d = 0; d < DD; d++) FMA2(acc, aq[d], ak[d], acc);
    unsigned lo, hi;
    UNPACK2(lo, hi, acc);
    s_reg[0] += cf * __uint_as_float(lo);
    s_reg[1] += cf * __uint_as_float(hi);
}

__global__ void __launch_bounds__(THREADS, 1)
tp_attn_kernel(const float* __restrict__ Tg, const float* __restrict__ Sg,
               const float* __restrict__ Wq, const float* __restrict__ Wk,
               const float* __restrict__ Wv, const float* __restrict__ w2,
               const float* __restrict__ lsw, const float* __restrict__ lsb,
               const float* __restrict__ lvw, const float* __restrict__ lvb,
               float* __restrict__ outT, float* __restrict__ out2) {
    extern __shared__ float smem[];
    float* T_s  = smem + OFF_T;
    float* SBt  = smem + OFF_SBT;
    float* PB   = smem + OFF_PB;
    float* SS2  = smem + OFF_SS2;
    float* WREG = smem + OFF_WREG;
    float* TU_s = T_s;                       // overlay after fused passes

    float* WQc = WREG;
    float* WKc = WREG + WTILE;
    float* WVc = WREG + 2 * WTILE;

    const int tid   = threadIdx.x;
    const int lane  = tid & 31;
    const int wid   = tid >> 5;
    const int v     = tid & 127;
    const int ng    = (tid >> 7) * 2;        // node pair base: 0,2,4,6,8,10
    const int node0 = blockIdx.x * NB;

    // ---- stage T tile: global [n][u][9] -> smem [u][d][n]; stage S -> SS2[c][n]
    {
        const float4* g4 = reinterpret_cast<const float4*>(Tg + (size_t)node0 * (FDIM * DTOT));
        for (int i = tid; i < 3456; i += THREADS) {
            float4 t = g4[i];
            float a[4] = { t.x, t.y, t.z, t.w };
            int e = i << 2;
            #pragma unroll
            for (int z = 0; z < 4; z++) {
                int ee = e + z;
                int n = ee / 1152;
                int r = ee - n * 1152;
                int u = r / 9;
                int d = r - u * 9;
                T_s[(u * 9 + d) * 12 + n] = a[z];
            }
        }
        if (tid < 384) {
            float4 t = reinterpret_cast<const float4*>(Sg + (size_t)node0 * FDIM)[tid];
            float a[4] = { t.x, t.y, t.z, t.w };
            int e = tid << 2;
            #pragma unroll
            for (int z = 0; z < 4; z++) {
                int ee = e + z;
                int n = ee >> 7;
                int c = ee & 127;
                SS2[c * 12 + n] = a[z];
            }
        }
    }

    float s_reg[2] = { 0.f, 0.f };
    ull av2[5], av1[3], av0[1];

    // ---- fused q/k/v passes, irrep l=2 first (peak regs when nothing carried)
    {
        ull aq[5], ak[5];
        #pragma unroll
        for (int d = 0; d < 5; d++) { aq[d] = 0ull; ak[d] = 0ull; av2[d] = 0ull; }
        #pragma unroll 1
        for (int c = 0; c < 2; c++) {
            __syncthreads();
            stage_wchunk(WQc, Wq + 32768, c, tid);
            stage_wchunk(WKc, Wk + 32768, c, tid);
            stage_wchunk(WVc, Wv + 32768, c, tid);
            __syncthreads();
            fused_chunk<4, 5>(T_s, WQc, WKc, WVc, v, ng, c, aq, ak, av2);
        }
        finalize_qk<5>(aq, ak, 0.0020171788261496963f, s_reg);  // (1/sqrt15)/128
    }
    {
        ull aq[3], ak[3];
        #pragma unroll
        for (int d = 0; d < 3; d++) { aq[d] = 0ull; ak[d] = 0ull; av1[d] = 0ull; }
        #pragma unroll 1
        for (int c = 0; c < 2; c++) {
            __syncthreads();
            stage_wchunk(WQc, Wq + 16384, c, tid);
            stage_wchunk(WKc, Wk + 16384, c, tid);
            stage_wchunk(WVc, Wv + 16384, c, tid);
            __syncthreads();
            fused_chunk<1, 3>(T_s, WQc, WKc, WVc, v, ng, c, aq, ak, av1);
        }
        finalize_qk<3>(aq, ak, 0.0026041666666666665f, s_reg);  // (1/3)/128
    }
    {
        ull aq[1], ak[1];
        aq[0] = 0ull; ak[0] = 0ull; av0[0] = 0ull;
        #pragma unroll 1
        for (int c = 0; c < 2; c++) {
            __syncthreads();
            stage_wchunk(WQc, Wq, c, tid);
            stage_wchunk(WKc, Wk, c, tid);
            stage_wchunk(WVc, Wv, c, tid);
            __syncthreads();
            fused_chunk<0, 1>(T_s, WQc, WKc, WVc, v, ng, c, aq, ak, av0);
        }
        finalize_qk<1>(aq, ak, 0.0045105489780439515f, s_reg);  // (1/sqrt3)/128
    }

    // s -> SBt[v][n]
    SBt[v * 12 + ng + 0] = s_reg[0];
    SBt[v * 12 + ng + 1] = s_reg[1];
    __syncthreads();   // all fused reads of WREG done; SBt ready

    // ---- stage ls_w untransposed [j][129] (conflict-free scalar copy)
    for (int i = tid; i < 32768; i += THREADS) {
        int jrow = i >> 7;
        int u    = i & 127;
        WREG[jrow * 129 + u] = lsw[i];
    }
    __syncthreads();

    // ---- logits: 2 warps per node; each lane owns 4 of 128 j in its half
    {
        int n    = wid >> 1;
        int half = wid & 1;
        float acc[4] = { 0.f, 0.f, 0.f, 0.f };
        #pragma unroll 2
        for (int u = 0; u < 128; u++) {
            float sv = SBt[u * 12 + n];
            #pragma unroll
            for (int kk = 0; kk < 4; kk++) {
                int j = half * 128 + (kk << 5) + lane;
                acc[kk] = fmaf(sv, WREG[j * 129 + u], acc[kk]);
            }
        }
        #pragma unroll
        for (int kk = 0; kk < 4; kk++) {
            int j = half * 128 + (kk << 5) + lane;
            PB[n * 256 + j] = acc[kk] + lsb[j];
        }
    }
    __syncthreads();

    // ---- softmax: warp per node (first 12 warps)
    if (wid < 12) {
        int n = wid;
        float acc[8];
        #pragma unroll
        for (int kk = 0; kk < 8; kk++) acc[kk] = PB[n * 256 + (kk << 5) + lane];
        float m = acc[0];
        #pragma unroll
        for (int kk = 1; kk < 8; kk++) m = fmaxf(m, acc[kk]);
        #pragma unroll
        for (int off = 16; off > 0; off >>= 1)
            m = fmaxf(m, __shfl_xor_sync(0xffffffffu, m, off));
        float ssum = 0.f;
        #pragma unroll
        for (int kk = 0; kk < 8; kk++) { acc[kk] = __expf(acc[kk] - m); ssum += acc[kk]; }
        #pragma unroll
        for (int off = 16; off > 0; off >>= 1)
            ssum += __shfl_xor_sync(0xffffffffu, ssum, off);
        float inv = 1.f / ssum;
        #pragma unroll
        for (int kk = 0; kk < 8; kk++)
            PB[n * 256 + (kk << 5) + lane] = acc[kk] * inv;
    }
    __syncthreads();

    // ---- TU: apply full scale (sd * w2 / sqrtF) from registers, store to smem overlay
    {
        const float INV_SQRT_F = 0.08838834764831845f;
        float w20 = w2[v]       * INV_SQRT_F;
        float w21 = w2[128 + v] * INV_SQRT_F;
        float w22 = w2[256 + v] * INV_SQRT_F;
        float sd0 = PB[(ng + 0) * 256 + 128 + v];
        float sd1 = PB[(ng + 1) * 256 + 128 + v];
        float* t0 = TU_s + (ng + 0) * 1152 + v * 9;
        float* t1 = TU_s + (ng + 1) * 1152 + v * 9;
        unsigned lo, hi;
        UNPACK2(lo, hi, av0[0]);
        t0[0] = sd0 * w20 * __uint_as_float(lo);
        t1[0] = sd1 * w20 * __uint_as_float(hi);
        #pragma unroll
        for (int d = 0; d < 3; d++) {
            UNPACK2(lo, hi, av1[d]);
            t0[1 + d] = sd0 * w21 * __uint_as_float(lo);
            t1[1 + d] = sd1 * w21 * __uint_as_float(hi);
        }
        #pragma unroll
        for (int d = 0; d < 5; d++) {
            UNPACK2(lo, hi, av2[d]);
            t0[4 + d] = sd0 * w22 * __uint_as_float(lo);
            t1[4 + d] = sd1 * w22 * __uint_as_float(hi);
        }
    }

    // ---- stage lvw [v][129] (overwrites ls_w region; logits reads done)
    for (int i = tid; i < 16384; i += THREADS) {
        int vrow = i >> 7;
        int u    = i & 127;
        WREG[vrow * 129 + u] = lvw[i];
    }
    __syncthreads();

    // ---- out2: su * silu(S @ lvs_w^T + b)
    {
        ull acc2 = 0ull;
        #pragma unroll 2
        for (int c = 0; c < 128; c++) {
            float w = WREG[v * 129 + c];
            ull w2p;
            PACKDUP(w2p, w);
            ull t = *reinterpret_cast<const ull*>(SS2 + c * 12 + ng);
            FMA2(acc2, w2p, t, acc2);
        }
        float b = lvb[v];
        unsigned lo, hi;
        UNPACK2(lo, hi, acc2);
        float zz[2] = { __uint_as_float(lo), __uint_as_float(hi) };
        #pragma unroll
        for (int j = 0; j < 2; j++) {
            int n = ng + j;
            float z   = zz[j] + b;
            float sig = 1.f / (1.f + __expf(-z));
            out2[(size_t)(node0 + n) * FDIM + v] = PB[n * 256 + v] * (z * sig);
        }
    }

    // ---- flush TU: pure coalesced float4 copy (TU writes synced above)
    {
        float4* gout = reinterpret_cast<float4*>(outT + (size_t)node0 * (FDIM * DTOT));
        const float4* s4 = reinterpret_cast<const float4*>(TU_s);
        for (int i = tid; i < 3456; i += THREADS)
            gout[i] = s4[i];
    }
}

extern "C" void kernel_launch(void* const* d_in, const int* in_sizes, int n_in,
                              void* d_out, int out_size) {
    const float* Tg  = (const float*)d_in[0];
    const float* Sg  = (const float*)d_in[1];
    const float* Wq  = (const float*)d_in[2];
    const float* Wk  = (const float*)d_in[3];
    const float* Wv  = (const float*)d_in[4];
    const float* w2  = (const float*)d_in[5];
    const float* lsw = (const float*)d_in[6];
    const float* lsb = (const float*)d_in[7];
    const float* lvw = (const float*)d_in[8];
    const float* lvb = (const float*)d_in[9];

    float* out  = (float*)d_out;
    float* outT = out;
    float* out2 = out + (size_t)NODES * FDIM * DTOT;

    const int smem_bytes = SMEM_FLOATS * 4;   // 211968
    cudaFuncSetAttribute(tp_attn_kernel,
                         cudaFuncAttributeMaxDynamicSharedMemorySize, smem_bytes);
    tp_attn_kernel<<<NODES / NB, THREADS, smem_bytes>>>(
        Tg, Sg, Wq, Wk, Wv, w2, lsw, lsb, lvw, lvb, outT, out2);
}

// round 16
// speedup vs baseline: 1.7210x; 1.7210x over previous
#include <cuda_runtime.h>
#include <cuda_fp16.h>
#include <cstdint>
#include <cstddef>

#define NODES 49152
#define FDIM  128
#define DTOT  9

// ---------------- device scratch (no allocation) ----------------
static __device__ __align__(16) __half g_Thi[(size_t)DTOT * NODES * FDIM];   // [d][n][u]
static __device__ __align__(16) __half g_Tlo[(size_t)DTOT * NODES * FDIM];
static __device__ __align__(16) float  g_TU [(size_t)DTOT * NODES * FDIM];   // [d][n][v]
static __device__ __align__(16) float  g_SU [(size_t)NODES * FDIM];          // su (p[:, :128])
static __device__ __align__(16) __half g_Whi[3 * 49152];                     // Wq[l]|Wk[l]|Wv[l]
static __device__ __align__(16) __half g_Wlo[3 * 49152];
static __device__ __align__(16) __half g_LShi[32768];                        // ls_w [256][128]
static __device__ __align__(16) __half g_LSlo[32768];
static __device__ __align__(16) __half g_LVhi[16384];                        // lvs_w [128][128]
static __device__ __align__(16) __half g_LVlo[16384];

// smem tile geometry: rows x 136 halves (272 B pitch, 68 words)
#define TB    34816          // 128-row tile bytes
#define R_A   4096
#define R_B   77824
#define R_C   151552
#define SM_MAIN  221184      // R_C + 2*TB
#define SM_OUT2  147456      // R_B + 2*TB
#define LPITCH 264           // logit buffer pitch (floats)

// ---------------- mma.sync m16n8k16 fp16 -> fp32 ----------------
static __device__ __forceinline__ void mma16816(float* d,
    uint32_t a0, uint32_t a1, uint32_t a2, uint32_t a3, uint32_t b0, uint32_t b1) {
    asm volatile("mma.sync.aligned.m16n8k16.row.col.f32.f16.f16.f32 "
        "{%0,%1,%2,%3}, {%4,%5,%6,%7}, {%8,%9}, {%0,%1,%2,%3};"
        : "+f"(d[0]), "+f"(d[1]), "+f"(d[2]), "+f"(d[3])
        : "r"(a0), "r"(a1), "r"(a2), "r"(a3), "r"(b0), "r"(b1));
}

// one K=128 GEMM pass: acc[2 m-tiles][8 n-tiles][4], A [M][K128], B stored [N][K128]
static __device__ __forceinline__ void gemm_pair(float* acc,
    const uint32_t* __restrict__ A, const uint32_t* __restrict__ B,
    int m0, int n0, int g, int tg) {
    #pragma unroll
    for (int kt = 0; kt < 8; kt++) {
        const int kw = kt * 8 + tg;
        uint32_t a[2][4];
        #pragma unroll
        for (int mt = 0; mt < 2; mt++) {
            int r = (m0 + mt * 16 + g) * 68 + kw;
            a[mt][0] = A[r];
            a[mt][1] = A[r + 8 * 68];
            a[mt][2] = A[r + 4];
            a[mt][3] = A[r + 8 * 68 + 4];
        }
        #pragma unroll
        for (int nt = 0; nt < 8; nt++) {
            int rb = (n0 + nt * 8 + g) * 68 + kw;
            uint32_t b0 = B[rb], b1 = B[rb + 4];
            #pragma unroll
            for (int mt = 0; mt < 2; mt++)
                mma16816(acc + (mt * 8 + nt) * 4, a[mt][0], a[mt][1], a[mt][2], a[mt][3], b0, b1);
        }
    }
}
// split-precision: hi*hi + hi*lo + lo*hi
static __device__ __forceinline__ void gemm_split(float* acc,
    const uint32_t* Ah, const uint32_t* Al, const uint32_t* Bh, const uint32_t* Bl,
    int m0, int n0, int g, int tg) {
    gemm_pair(acc, Ah, Bh, m0, n0, g, tg);
    gemm_pair(acc, Ah, Bl, m0, n0, g, tg);
    gemm_pair(acc, Al, Bh, m0, n0, g, tg);
}

// stage a [rows][128] half tile (row-major global) into pitched smem (256 threads)
static __device__ __forceinline__ void stage_h(char* dst, const __half* __restrict__ src,
                                               int rows, int tid) {
    const uint4* s4 = reinterpret_cast<const uint4*>(src);
    for (int c = tid; c < rows * 16; c += 256) {
        int row = c >> 4, cb = (c & 15) * 16;
        *reinterpret_cast<uint4*>(dst + row * 272 + cb) = s4[c];
    }
}
// stage [128][128] fp32 tile split into hi/lo fp16 pitched tiles
static __device__ __forceinline__ void stage_split_f32(char* dh, char* dl,
                                                       const float* __restrict__ src, int tid) {
    const float4* s4 = reinterpret_cast<const float4*>(src);
    for (int c = tid; c < 2048; c += 256) {
        int row = c >> 4, cb = (c & 15) * 16;
        float4 x = s4[2 * c], y = s4[2 * c + 1];
        float v[8] = { x.x, x.y, x.z, x.w, y.x, y.y, y.z, y.w };
        uint32_t hw[4], lw[4];
        #pragma unroll
        for (int i = 0; i < 4; i++) {
            __half2 h2 = __floats2half2_rn(v[2 * i], v[2 * i + 1]);
            __half2 l2 = __floats2half2_rn(v[2 * i]     - __half2float(__low2half(h2)),
                                           v[2 * i + 1] - __half2float(__high2half(h2)));
            hw[i] = *reinterpret_cast<uint32_t*>(&h2);
            lw[i] = *reinterpret_cast<uint32_t*>(&l2);
        }
        *reinterpret_cast<uint4*>(dh + row * 272 + cb) = make_uint4(hw[0], hw[1], hw[2], hw[3]);
        *reinterpret_cast<uint4*>(dl + row * 272 + cb) = make_uint4(lw[0], lw[1], lw[2], lw[3]);
    }
}

// ---------------- K1: T [n][u][9] fp32 -> [d][n][u] fp16 hi/lo ----------------
__global__ __launch_bounds__(256) void k_splitT(const float* __restrict__ Tg) {
    extern __shared__ char sm[];
    __half* hi_s = reinterpret_cast<__half*>(sm);            // [9][32][128]
    __half* lo_s = hi_s + 9 * 32 * 128;
    const int tid = threadIdx.x;
    const int node0 = blockIdx.x * 32;
    const float4* g4 = reinterpret_cast<const float4*>(Tg + (size_t)node0 * 1152);
    #pragma unroll
    for (int it = 0; it < 36; it++) {
        int i = it * 256 + tid;
        float4 t = g4[i];
        float a[4] = { t.x, t.y, t.z, t.w };
        int e = i << 2;
        #pragma unroll
        for (int z = 0; z < 4; z++) {
            int ee = e + z;
            int nl = ee / 1152;
            int r  = ee - nl * 1152;
            int u  = r / 9;
            int d  = r - u * 9;
            __half h = __float2half_rn(a[z]);
            int idx = (d * 32 + nl) * 128 + u;
            hi_s[idx] = h;
            lo_s[idx] = __float2half_rn(a[z] - __half2float(h));
        }
    }
    __syncthreads();
    const uint4* h4 = reinterpret_cast<const uint4*>(hi_s);
    const uint4* l4 = reinterpret_cast<const uint4*>(lo_s);
    #pragma unroll
    for (int it = 0; it < 18; it++) {
        int j = it * 256 + tid;           // 4608 uint4
        int d = j >> 9;
        int w = j & 511;
        reinterpret_cast<uint4*>(g_Thi + ((size_t)d * NODES + node0) * 128)[w] = h4[j];
        reinterpret_cast<uint4*>(g_Tlo + ((size_t)d * NODES + node0) * 128)[w] = l4[j];
    }
}

// ---------------- K2: split weights (all L slices) ----------------
__global__ __launch_bounds__(256) void k_splitW(const float* __restrict__ Wq, const float* __restrict__ Wk,
                                                const float* __restrict__ Wv, const float* __restrict__ lsw,
                                                const float* __restrict__ lvw) {
    int idx = blockIdx.x * 256 + threadIdx.x;    // 0..196607
    float x;
    __half *dh, *dl;
    if (idx < 49152)       { x = Wq[idx];           dh = g_Whi + idx;           dl = g_Wlo + idx; }
    else if (idx < 98304)  { x = Wk[idx - 49152];   dh = g_Whi + idx;           dl = g_Wlo + idx; }
    else if (idx < 147456) { x = Wv[idx - 98304];   dh = g_Whi + idx;           dl = g_Wlo + idx; }
    else if (idx < 180224) { x = lsw[idx - 147456]; dh = g_LShi + idx - 147456; dl = g_LSlo + idx - 147456; }
    else                   { x = lvw[idx - 180224]; dh = g_LVhi + idx - 180224; dl = g_LVlo + idx - 180224; }
    __half h = __float2half_rn(x);
    *dh = h;
    *dl = __float2half_rn(x - __half2float(h));
}

// ---------------- K3: main mma kernel (384 CTAs x 128 nodes, 256 thr) ----------------
__global__ __launch_bounds__(256, 1) void k_main(const float* __restrict__ w2,
                                                 const float* __restrict__ lsb) {
    extern __shared__ char sm[];
    float* w2s  = reinterpret_cast<float*>(sm);          // 384 floats
    float* lsbs = reinterpret_cast<float*>(sm + 1536);   // 256 floats
    const int tid  = threadIdx.x;
    const int lane = tid & 31;
    const int wid  = tid >> 5;
    const int g    = lane >> 2;
    const int tg   = lane & 3;
    const int m0   = (wid & 3) * 32;
    const int n0   = (wid >> 2) * 64;
    const int node0 = blockIdx.x * 128;

    for (int i = tid; i < 640; i += 256) {
        if (i < 384) w2s[i] = w2[i];
        else         lsbs[i - 384] = lsb[i - 384];
    }

    uint32_t* WAh = reinterpret_cast<uint32_t*>(sm + R_A);
    uint32_t* WAl = reinterpret_cast<uint32_t*>(sm + R_A + TB);
    uint32_t* WBh = reinterpret_cast<uint32_t*>(sm + R_B);
    uint32_t* WBl = reinterpret_cast<uint32_t*>(sm + R_B + TB);
    uint32_t* ACh = reinterpret_cast<uint32_t*>(sm + R_C);
    uint32_t* ACl = reinterpret_cast<uint32_t*>(sm + R_C + TB);

    const int   dlo[3] = { 0, 1, 4 };
    const int   dhi[3] = { 1, 4, 9 };
    const float cfs[3] = { 0.0045105489780439515f,   // (1/sqrt3)/128
                           0.0026041666666666665f,   // (1/3)/128
                           0.0020171788261496963f }; // (1/sqrt15)/128

    float sF[64];
    #pragma unroll
    for (int i = 0; i < 64; i++) sF[i] = 0.f;

    // ===== q,k pass (per-irrep weights) =====
    #pragma unroll 1
    for (int l = 0; l < 3; l++) {
        stage_h(sm + R_A,      g_Whi +         l * 16384, 128, tid);
        stage_h(sm + R_A + TB, g_Wlo +         l * 16384, 128, tid);
        stage_h(sm + R_B,      g_Whi + 49152 + l * 16384, 128, tid);
        stage_h(sm + R_B + TB, g_Wlo + 49152 + l * 16384, 128, tid);
        const float cf = cfs[l];
        #pragma unroll 1
        for (int d = dlo[l]; d < dhi[l]; d++) {
            stage_h(sm + R_C,      g_Thi + ((size_t)d * NODES + node0) * 128, 128, tid);
            stage_h(sm + R_C + TB, g_Tlo + ((size_t)d * NODES + node0) * 128, 128, tid);
            __syncthreads();
            float qF[64], kF[64];
            #pragma unroll
            for (int i = 0; i < 64; i++) { qF[i] = 0.f; kF[i] = 0.f; }
            gemm_split(qF, ACh, ACl, WAh, WAl, m0, n0, g, tg);
            gemm_split(kF, ACh, ACl, WBh, WBl, m0, n0, g, tg);
            #pragma unroll
            for (int i = 0; i < 64; i++) sF[i] = fmaf(cf * qF[i], kF[i], sF[i]);
            __syncthreads();
        }
    }

    // ===== write s as hi/lo fp16 A-tile into R_A =====
    #pragma unroll
    for (int mt = 0; mt < 2; mt++)
    #pragma unroll
    for (int nt = 0; nt < 8; nt++) {
        float* e = sF + (mt * 8 + nt) * 4;
        int r0 = m0 + mt * 16 + g, r1 = r0 + 8;
        int cw = (n0 + nt * 8) / 2 + tg;
        __half2 h0 = __floats2half2_rn(e[0], e[1]);
        __half2 l0 = __floats2half2_rn(e[0] - __half2float(__low2half(h0)),
                                       e[1] - __half2float(__high2half(h0)));
        __half2 h1 = __floats2half2_rn(e[2], e[3]);
        __half2 l1 = __floats2half2_rn(e[2] - __half2float(__low2half(h1)),
                                       e[3] - __half2float(__high2half(h1)));
        WAh[r0 * 68 + cw] = *reinterpret_cast<uint32_t*>(&h0);
        WAl[r0 * 68 + cw] = *reinterpret_cast<uint32_t*>(&l0);
        WAh[r1 * 68 + cw] = *reinterpret_cast<uint32_t*>(&h1);
        WAl[r1 * 68 + cw] = *reinterpret_cast<uint32_t*>(&l1);
    }
    // stage ls (256 rows) hi -> R_B, lo -> R_C
    stage_h(sm + R_B, g_LShi, 256, tid);
    stage_h(sm + R_C, g_LSlo, 256, tid);
    __syncthreads();

    // ===== logits GEMM (two N-halves) =====
    float lg0[64], lg1[64];
    #pragma unroll
    for (int i = 0; i < 64; i++) { lg0[i] = 0.f; lg1[i] = 0.f; }
    {
        const uint32_t* LBh = reinterpret_cast<const uint32_t*>(sm + R_B);
        const uint32_t* LBl = reinterpret_cast<const uint32_t*>(sm + R_C);
        gemm_split(lg0, WAh, WAl, LBh, LBl, m0, n0,       g, tg);
        gemm_split(lg1, WAh, WAl, LBh, LBl, m0, n0 + 128, g, tg);
    }
    __syncthreads();

    // dump logits fp32 into LB (pitch LPITCH) over R_B/R_C
    float* LB = reinterpret_cast<float*>(sm + R_B);
    #pragma unroll
    for (int mt = 0; mt < 2; mt++)
    #pragma unroll
    for (int nt = 0; nt < 8; nt++) {
        int r0 = m0 + mt * 16 + g, r1 = r0 + 8;
        int c0 = n0 + nt * 8 + tg * 2;
        float* e0 = lg0 + (mt * 8 + nt) * 4;
        float* e1 = lg1 + (mt * 8 + nt) * 4;
        LB[r0 * LPITCH + c0]       = e0[0];  LB[r0 * LPITCH + c0 + 1]       = e0[1];
        LB[r1 * LPITCH + c0]       = e0[2];  LB[r1 * LPITCH + c0 + 1]       = e0[3];
        LB[r0 * LPITCH + 128 + c0] = e1[0];  LB[r0 * LPITCH + 128 + c0 + 1] = e1[1];
        LB[r1 * LPITCH + 128 + c0] = e1[2];  LB[r1 * LPITCH + 128 + c0 + 1] = e1[3];
    }
    __syncthreads();

    // ===== softmax: warp owns 16 nodes; su -> g_SU, sd -> sd_s (R_A) =====
    float* sd_s = reinterpret_cast<float*>(sm + R_A);    // [128][136]
    #pragma unroll 1
    for (int r = 0; r < 16; r++) {
        int n = wid * 16 + r;
        float x[8], M = -1e30f;
        #pragma unroll
        for (int k8 = 0; k8 < 8; k8++) {
            x[k8] = LB[n * LPITCH + lane + 32 * k8] + lsbs[lane + 32 * k8];
            M = fmaxf(M, x[k8]);
        }
        #pragma unroll
        for (int off = 16; off > 0; off >>= 1)
            M = fmaxf(M, __shfl_xor_sync(0xffffffffu, M, off));
        float Ssum = 0.f;
        #pragma unroll
        for (int k8 = 0; k8 < 8; k8++) { x[k8] = __expf(x[k8] - M); Ssum += x[k8]; }
        #pragma unroll
        for (int off = 16; off > 0; off >>= 1)
            Ssum += __shfl_xor_sync(0xffffffffu, Ssum, off);
        float inv = 1.f / Ssum;
        #pragma unroll
        for (int k8 = 0; k8 < 4; k8++)
            g_SU[(size_t)(node0 + n) * 128 + lane + 32 * k8] = x[k8] * inv;
        #pragma unroll
        for (int k8 = 4; k8 < 8; k8++)
            sd_s[n * 136 + lane + 32 * (k8 - 4)] = x[k8] * inv;
    }
    __syncthreads();

    // ===== v pass (per-irrep Wv) =====
    const float INVF = 0.08838834764831845f;
    #pragma unroll 1
    for (int l = 0; l < 3; l++) {
        stage_h(sm + R_B,      g_Whi + 98304 + l * 16384, 128, tid);
        stage_h(sm + R_B + TB, g_Wlo + 98304 + l * 16384, 128, tid);
        const float* w2r = w2s + l * 128;
        #pragma unroll 1
        for (int d = dlo[l]; d < dhi[l]; d++) {
            stage_h(sm + R_C,      g_Thi + ((size_t)d * NODES + node0) * 128, 128, tid);
            stage_h(sm + R_C + TB, g_Tlo + ((size_t)d * NODES + node0) * 128, 128, tid);
            __syncthreads();
            float vF[64];
            #pragma unroll
            for (int i = 0; i < 64; i++) vF[i] = 0.f;
            gemm_split(vF, ACh, ACl, WBh, WBl, m0, n0, g, tg);
            float* tub = g_TU + ((size_t)d * NODES + node0) * 128;
            #pragma unroll
            for (int mt = 0; mt < 2; mt++)
            #pragma unroll
            for (int nt = 0; nt < 8; nt++) {
                float* e = vF + (mt * 8 + nt) * 4;
                int r0 = m0 + mt * 16 + g, r1 = r0 + 8;
                int c0 = n0 + nt * 8 + tg * 2;
                float wa = w2r[c0] * INVF, wb = w2r[c0 + 1] * INVF;
                float2 o0 = make_float2(e[0] * sd_s[r0 * 136 + c0] * wa,
                                        e[1] * sd_s[r0 * 136 + c0 + 1] * wb);
                float2 o1 = make_float2(e[2] * sd_s[r1 * 136 + c0] * wa,
                                        e[3] * sd_s[r1 * 136 + c0 + 1] * wb);
                *reinterpret_cast<float2*>(tub + (size_t)r0 * 128 + c0) = o0;
                *reinterpret_cast<float2*>(tub + (size_t)r1 * 128 + c0) = o1;
            }
            __syncthreads();
        }
    }
}

// ---------------- K4: out2 = su * silu(S @ lvw^T + b) ----------------
__global__ __launch_bounds__(256, 1) void k_out2(const float* __restrict__ Sg,
                                                 const float* __restrict__ lvb,
                                                 float* __restrict__ out2) {
    extern __shared__ char sm[];
    float* lvbs = reinterpret_cast<float*>(sm);
    const int tid  = threadIdx.x;
    const int lane = tid & 31;
    const int wid  = tid >> 5;
    const int g    = lane >> 2;
    const int tg   = lane & 3;
    const int m0   = (wid & 3) * 32;
    const int n0   = (wid >> 2) * 64;
    const int node0 = blockIdx.x * 128;

    for (int i = tid; i < 128; i += 256) lvbs[i] = lvb[i];
    stage_split_f32(sm + R_A, sm + R_A + TB, Sg + (size_t)node0 * 128, tid);
    stage_h(sm + R_B,      g_LVhi, 128, tid);
    stage_h(sm + R_B + TB, g_LVlo, 128, tid);
    __syncthreads();

    float zF[64];
    #pragma unroll
    for (int i = 0; i < 64; i++) zF[i] = 0.f;
    gemm_split(zF,
               reinterpret_cast<const uint32_t*>(sm + R_A),
               reinterpret_cast<const uint32_t*>(sm + R_A + TB),
               reinterpret_cast<const uint32_t*>(sm + R_B),
               reinterpret_cast<const uint32_t*>(sm + R_B + TB),
               m0, n0, g, tg);

    #pragma unroll
    for (int mt = 0; mt < 2; mt++)
    #pragma unroll
    for (int nt = 0; nt < 8; nt++) {
        float* e = zF + (mt * 8 + nt) * 4;
        int r0 = m0 + mt * 16 + g, r1 = r0 + 8;
        int c0 = n0 + nt * 8 + tg * 2;
        float b0 = lvbs[c0], b1 = lvbs[c0 + 1];
        float2 o0, o1;
        {
            float z0 = e[0] + b0, z1 = e[1] + b1;
            float su0 = g_SU[(size_t)(node0 + r0) * 128 + c0];
            float su1 = g_SU[(size_t)(node0 + r0) * 128 + c0 + 1];
            o0 = make_float2(su0 * (z0 / (1.f + __expf(-z0))),
                             su1 * (z1 / (1.f + __expf(-z1))));
            float z2 = e[2] + b0, z3 = e[3] + b1;
            float su2 = g_SU[(size_t)(node0 + r1) * 128 + c0];
            float su3 = g_SU[(size_t)(node0 + r1) * 128 + c0 + 1];
            o1 = make_float2(su2 * (z2 / (1.f + __expf(-z2))),
                             su3 * (z3 / (1.f + __expf(-z3))));
        }
        *reinterpret_cast<float2*>(out2 + (size_t)(node0 + r0) * 128 + c0) = o0;
        *reinterpret_cast<float2*>(out2 + (size_t)(node0 + r1) * 128 + c0) = o1;
    }
}

// ---------------- K5: g_TU [d][n][v] -> out [n][v][d] ----------------
__global__ __launch_bounds__(256) void k_outT(float* __restrict__ outT) {
    extern __shared__ char sm[];
    float* ts = reinterpret_cast<float*>(sm);   // [9][32][128]
    const int tid = threadIdx.x;
    const int node0 = blockIdx.x * 32;
    #pragma unroll
    for (int it = 0; it < 36; it++) {
        int j = it * 256 + tid;                 // 9216 float4
        int d = j >> 10;
        int w = j & 1023;
        reinterpret_cast<float4*>(ts)[j] =
            reinterpret_cast<const float4*>(g_TU + ((size_t)d * NODES + node0) * 128)[w];
    }
    __syncthreads();
    float4* o4 = reinterpret_cast<float4*>(outT + (size_t)node0 * 1152);
    #pragma unroll
    for (int it = 0; it < 36; it++) {
        int i = it * 256 + tid;
        int e = i << 2;
        int nl = e / 1152;
        int r  = e - nl * 1152;
        float o[4];
        #pragma unroll
        for (int z = 0; z < 4; z++) {
            int rr = r + z;
            int v_ = rr / 9;
            int d  = rr - v_ * 9;
            o[z] = ts[(d * 32 + nl) * 128 + v_];
        }
        o4[i] = make_float4(o[0], o[1], o[2], o[3]);
    }
}

// ---------------- launch ----------------
extern "C" void kernel_launch(void* const* d_in, const int* in_sizes, int n_in,
                              void* d_out, int out_size) {
    const float* Tg  = (const float*)d_in[0];
    const float* Sg  = (const float*)d_in[1];
    const float* Wq  = (const float*)d_in[2];
    const float* Wk  = (const float*)d_in[3];
    const float* Wv  = (const float*)d_in[4];
    const float* w2  = (const float*)d_in[5];
    const float* lsw = (const float*)d_in[6];
    const float* lsb = (const float*)d_in[7];
    const float* lvw = (const float*)d_in[8];
    const float* lvb = (const float*)d_in[9];

    float* out  = (float*)d_out;
    float* outT = out;
    float* out2 = out + (size_t)NODES * FDIM * DTOT;

    cudaFuncSetAttribute(k_splitT, cudaFuncAttributeMaxDynamicSharedMemorySize, 147456);
    cudaFuncSetAttribute(k_main,   cudaFuncAttributeMaxDynamicSharedMemorySize, SM_MAIN);
    cudaFuncSetAttribute(k_out2,   cudaFuncAttributeMaxDynamicSharedMemorySize, SM_OUT2);
    cudaFuncSetAttribute(k_outT,   cudaFuncAttributeMaxDynamicSharedMemorySize, 147456);

    k_splitT<<<NODES / 32, 256, 147456>>>(Tg);
    k_splitW<<<768, 256>>>(Wq, Wk, Wv, lsw, lvw);
    k_main<<<NODES / 128, 256, SM_MAIN>>>(w2, lsb);
    k_out2<<<NODES / 128, 256, SM_OUT2>>>(Sg, lvb, out2);
    k_outT<<<NODES / 32, 256, 147456>>>(outT);
}